// round 13
// baseline (speedup 1.0000x reference)
#include <cuda_runtime.h>
#include <cuda_bf16.h>
#include <cfloat>
#include <cstdint>

// ---------------------------------------------------------------------------
// RetinaNet postprocess, round 13: THREE kernels, each with a
// "last-finishing-block runs the serial epilogue" fusion (threadfence +
// completion counter; epilogue only reads fully-published data).
//   K1 prep+rank : grid prep (class-max, decode, slab emit score>CUTOFF);
//                  last block comparison-ranks the slab -> sorted arrays
//   K2 pair+scan : 64 blocks build upper-triangular IoU mask rows; last
//                  block's warp0 runs exact greedy with cp.async SMEM ring
//   K3 flag+final: grid tail-vs-snapshot flags (early-exit at nk==300);
//                  last block: serial reference greedy over survivors
//                  (normally none) + warp-per-keep argmax + output tuple
// Exactness: slab = {score > CUTOFF} is a clean cut in descending (score,idx)
// order; kept set monotone; tail path exact for any cut; slab overflow (>T0)
// => slab empty => everything flows through the exact serial tail path.
// ---------------------------------------------------------------------------

#define MAXA   262144
#define MAXDET 300
#define T0     2048
#define W0     32
#define NCH    8
#define PAIRB  64
#define TILE1  256
#define BLK1   1024
#define BLK2   256
#define BLK3   1024
#define PSTTHD 0.05f
#define CUTOFF 0.99990f
#define NMSTHD 0.5f

typedef unsigned long long ull;

__device__ float  g_keys [MAXA];
__device__ float4 g_boxes[MAXA];
__device__ float  g_areas[MAXA];
__device__ ull    g_ckeys[T0];
__device__ int    g_cidx [T0];
__device__ float4 g_cbox [T0];
__device__ float  g_carea[T0];
__device__ ull    g_mask [T0 * W0];
__device__ ull    g_skey [MAXA];
__device__ float4 g_kbox [MAXDET];
__device__ float  g_karea[MAXDET];
__device__ int    g_keep [MAXDET];
__device__ int    g_scnt;
__device__ int    g_nsurv;
__device__ int    g_nk;
__device__ int    g_overflow;
__device__ unsigned g_cnt1, g_cnt2, g_cnt3;

__device__ __forceinline__ bool sup_test(float x1, float y1, float x2, float y2, float ar,
                                         float X1, float Y1, float X2, float Y2, float AR)
{
    float xx1 = fmaxf(x1, X1);
    float yy1 = fmaxf(y1, Y1);
    float xx2 = fminf(x2, X2);
    float yy2 = fminf(y2, Y2);
    float inter = fmaxf(xx2 - xx1, 0.0f) * fmaxf(yy2 - yy1, 0.0f);
    float iou = inter / (ar + AR - inter + 1e-8f);
    return iou > NMSTHD;
}

__device__ __forceinline__ void cpa8(void* dst, const void* src)
{
    unsigned s = (unsigned)__cvta_generic_to_shared(dst);
    asm volatile("cp.async.ca.shared.global [%0], [%1], 8;" :: "r"(s), "l"(src) : "memory");
}
#define CPA_COMMIT()  asm volatile("cp.async.commit_group;" ::: "memory")
#define CPA_WAIT7()   asm volatile("cp.async.wait_group 7;" ::: "memory")
#define CPA_WAITALL() asm volatile("cp.async.wait_all;" ::: "memory")

// ===========================================================================
// K1: prep (grid) + rank (last block)
// ===========================================================================
__global__ void __launch_bounds__(BLK1)
prep_rank_kernel(const float* __restrict__ cls,
                 const float* __restrict__ reg,
                 const float* __restrict__ anc,
                 const int*   __restrict__ ph,
                 const int*   __restrict__ pw,
                 int A, int C)
{
    __shared__ union { unsigned srow[TILE1]; ull skeys[T0]; } sm;
    __shared__ int is_last;
    int t = threadIdx.x;
    int base = blockIdx.x * TILE1;

    // ---- prep: 256 anchors per 1024-thread block ----
    if (t < TILE1) sm.srow[t] = 0u;
    __syncthreads();

    if ((C & 3) == 0) {
        int f4r = C >> 2;
        int tot = TILE1 * f4r;
        const float4* cb = (const float4*)cls + (size_t)base * f4r;
        for (int i = t; i < tot; i += BLK1) {
            int r = i / f4r;
            if (base + r < A) {
                float4 v = cb[i];
                float m = fmaxf(fmaxf(v.x, v.y), fmaxf(v.z, v.w));
                atomicMax(&sm.srow[r], __float_as_uint(m));
            }
        }
    } else {
        for (int i = t; i < TILE1 * C; i += BLK1) {
            int r = i / C;
            if (base + r < A) {
                float m = cls[(size_t)(base + r) * C + (i % C)];
                atomicMax(&sm.srow[r], __float_as_uint(m));
            }
        }
    }
    __syncthreads();

    if (t < TILE1 && base + t < A) {
        int a = base + t;
        float m = __uint_as_float(sm.srow[t]);
        g_keys[a] = (m > PSTTHD) ? m : 0.0f;
        if (m > CUTOFF) {
            int p = atomicAdd(&g_scnt, 1);
            if (p < T0)
                g_ckeys[p] = ((ull)__float_as_uint(m) << 18) |
                             (ull)(0x3FFFFu - (unsigned)a);
        }
        float4 an = ((const float4*)anc)[a];
        float4 rg = ((const float4*)reg)[a];
        float bw = an.z - an.x;
        float bh = an.w - an.y;
        float cx = an.x + 0.5f * bw;
        float cy = an.y + 0.5f * bh;
        float pcx = cx + (rg.x * 0.1f) * bw;
        float pcy = cy + (rg.y * 0.1f) * bh;
        float pw_ = expf(rg.z * 0.2f) * bw;
        float ph_ = expf(rg.w * 0.2f) * bh;
        float Wd = pw ? (float)__ldg(pw) : 1024.0f;
        float Hd = ph ? (float)__ldg(ph) : 1024.0f;
        float x1 = fmaxf(pcx - 0.5f * pw_, 0.0f);
        float y1 = fmaxf(pcy - 0.5f * ph_, 0.0f);
        float x2 = fminf(pcx + 0.5f * pw_, Wd);
        float y2 = fminf(pcy + 0.5f * ph_, Hd);
        g_boxes[a] = make_float4(x1, y1, x2, y2);
        g_areas[a] = (x2 - x1) * (y2 - y1);
    }

    // ---- epilogue: last block ranks the slab ----
    __threadfence();
    __syncthreads();
    if (t == 0) {
        unsigned old = atomicAdd(&g_cnt1, 1u);
        is_last = (old == gridDim.x - 1u) ? 1 : 0;
    }
    __syncthreads();
    if (!is_last) return;
    __threadfence();

    int scnt = g_scnt;
    int n = (scnt > T0) ? 0 : scnt;
    for (int i = t; i < n; i += BLK1) sm.skeys[i] = g_ckeys[i];
    __syncthreads();
    for (int i = t; i < n; i += BLK1) {
        ull mykey = sm.skeys[i];
        int r = 0;
        #pragma unroll 4
        for (int j = 0; j < n; j++) r += (sm.skeys[j] > mykey) ? 1 : 0;
        int a = (int)(0x3FFFFu - (unsigned)(mykey & 0x3FFFFULL));
        g_cidx[r]  = a;
        g_cbox[r]  = g_boxes[a];
        g_carea[r] = g_areas[a];
    }
    if (t == 0) g_cnt1 = 0;
}

// ===========================================================================
// K2: pair (64 blocks) + scan (last block, warp0, cp.async ring)
// ===========================================================================
__global__ void __launch_bounds__(BLK2)
pair_scan_kernel()
{
    __shared__ union {
        struct { float4 scb[T0]; float sca[T0]; } p;
        struct { ull ring[NCH][16][32]; int spos[MAXDET]; } s;
    } sm;
    __shared__ int is_last;
    int t = threadIdx.x;
    int lane = t & 31;
    int scnt = g_scnt;
    int overflow = (scnt > T0) ? 1 : 0;
    int n = overflow ? 0 : scnt;

    // ---- pair: upper-triangular masks ----
    if (n > 0) {
        for (int i = t; i < n; i += BLK2) {
            sm.p.scb[i] = g_cbox[i];
            sm.p.sca[i] = g_carea[i];
        }
        __syncthreads();
        int items = n * W0;
        for (int it = blockIdx.x * BLK2 + t; it < items; it += PAIRB * BLK2) {
            int i = it >> 5;
            int w = it & 31;
            int jbase = w << 6;
            int jstart = max(jbase, i + 1);
            int jend   = min(jbase + 64, n);
            ull word = 0ULL;
            if (jstart < jend) {
                float4 bi = sm.p.scb[i];
                float  ai = sm.p.sca[i];
                for (int j = jstart; j < jend; j++) {
                    float4 bj = sm.p.scb[j];
                    if (sup_test(bi.x, bi.y, bi.z, bi.w, ai,
                                 bj.x, bj.y, bj.z, bj.w, sm.p.sca[j]))
                        word |= 1ULL << (j - jbase);
                }
            }
            g_mask[it] = word;
        }
    }

    // ---- epilogue: last block scans ----
    __threadfence();
    __syncthreads();
    if (t == 0) {
        unsigned old = atomicAdd(&g_cnt2, 1u);
        is_last = (old == gridDim.x - 1u) ? 1 : 0;
    }
    __syncthreads();
    if (!is_last) return;
    __threadfence();
    __syncthreads();                       // smem union repurposed below

    if (t < 32) {
        int nchunks = (n + 15) >> 4;
        for (int c = 0; c < NCH; c++) {
            int cb = c << 4;
            #pragma unroll
            for (int r = 0; r < 16; r++) {
                int i = cb + r;
                if (i < n) cpa8(&sm.s.ring[c][r][lane], &g_mask[(size_t)i * W0 + lane]);
            }
            CPA_COMMIT();
        }
        ull removed = 0ULL;
        int nk = 0;
        for (int c = 0; c < nchunks && nk < MAXDET; c++) {
            CPA_WAIT7();
            __syncwarp();
            int slot = c & (NCH - 1);
            int cb = c << 4;
            ull buf[16];
            #pragma unroll
            for (int r = 0; r < 16; r++) buf[r] = sm.s.ring[slot][r][lane];

            int lim = min(16, n - cb);
            int widx = cb >> 6;
            ull dec = 0ULL;
            if (lane == widx) {
                ull w = removed;
                for (int r = 0; r < lim; r++) {
                    int bit = (cb + r) & 63;
                    if (!((w >> bit) & 1ULL)) {
                        dec |= 1ULL << r;
                        w |= buf[r];
                    }
                }
                removed = w;
            }
            dec = __shfl_sync(0xffffffffu, dec, widx);
            while (dec) {
                int r = __ffsll(dec) - 1;
                dec &= dec - 1;
                removed |= buf[r];
                if (lane == 0) sm.s.spos[nk] = cb + r;
                nk++;
                if (nk >= MAXDET) break;
            }

            int pb = (c + NCH) << 4;
            #pragma unroll
            for (int r = 0; r < 16; r++) {
                int i = pb + r;
                if (i < n) cpa8(&sm.s.ring[slot][r][lane], &g_mask[(size_t)i * W0 + lane]);
            }
            CPA_COMMIT();
        }
        CPA_WAITALL();
        __syncwarp();
        for (int k = lane; k < nk; k += 32) {
            int p = sm.s.spos[k];
            g_keep[k]  = g_cidx[p];
            g_kbox[k]  = g_cbox[p];
            g_karea[k] = g_carea[p];
        }
        if (lane == 0) {
            g_nk = nk;
            g_overflow = overflow;
            g_scnt = 0;                    // next replay's prep starts clean
            g_nsurv = 0;                   // next kernel's flag starts clean
            g_cnt2 = 0;
        }
    }
}

// ===========================================================================
// K3: flag (grid) + serial tail + final output (last block)
// ===========================================================================
__global__ void __launch_bounds__(BLK3)
flag_final_kernel(const float* __restrict__ cls, int A, int C,
                  float* __restrict__ out)
{
    __shared__ float4 skb[MAXDET];
    __shared__ float  ska[MAXDET];
    __shared__ ull    sb[BLK3];
    __shared__ float4 swin;
    __shared__ float  swar;
    __shared__ int    is_last;
    int t = threadIdx.x;
    int lane = t & 31;
    int wrp = t >> 5;

    // ---- flag: tail vs snapshot ----
    int nk = g_nk;
    if (nk < MAXDET) {
        for (int k = t; k < nk; k += BLK3) {
            skb[k] = g_kbox[k];
            ska[k] = g_karea[k];
        }
        __syncthreads();
        int sovf = g_overflow;
        int a = blockIdx.x * BLK3 + t;
        if (a < A) {
            float key = g_keys[a];
            if (key > PSTTHD && (sovf || !(key > CUTOFF))) {
                float4 b = g_boxes[a];
                float ar = g_areas[a];
                bool sup = false;
                for (int k = 0; k < nk; k++) {
                    if (sup_test(b.x, b.y, b.z, b.w, ar,
                                 skb[k].x, skb[k].y, skb[k].z, skb[k].w, ska[k])) {
                        sup = true;
                        break;
                    }
                }
                if (!sup) {
                    int p = atomicAdd(&g_nsurv, 1);
                    g_skey[p] = ((ull)__float_as_uint(key) << 18) |
                                (ull)(0x3FFFFu - (unsigned)a);
                }
            }
        }
    }

    // ---- epilogue: last block does serial tail + final ----
    __threadfence();
    __syncthreads();
    if (t == 0) {
        unsigned old = atomicAdd(&g_cnt3, 1u);
        is_last = (old == gridDim.x - 1u) ? 1 : 0;
    }
    __syncthreads();
    if (!is_last) return;
    __threadfence();

    int nk3 = g_nk;
    int ns = g_nsurv;
    while (nk3 < MAXDET && ns > 0) {
        ull best = 0ULL;
        for (int i = t; i < ns; i += BLK3) {
            ull v = g_skey[i];
            if (v > best) best = v;
        }
        sb[t] = best;
        __syncthreads();
        for (int off = BLK3 / 2; off; off >>= 1) {
            if (t < off && sb[t + off] > sb[t]) sb[t] = sb[t + off];
            __syncthreads();
        }
        if (sb[0] == 0ULL) break;

        if (t == 0) {
            int a = (int)(0x3FFFFu - (unsigned)(sb[0] & 0x3FFFFULL));
            float4 b = g_boxes[a];
            float ar = g_areas[a];
            g_keep[nk3]  = a;
            g_kbox[nk3]  = b;
            g_karea[nk3] = ar;
            swin = b;
            swar = ar;
        }
        __syncthreads();
        float4 wb = swin;
        float war = swar;
        for (int i = t; i < ns; i += BLK3) {
            ull v = g_skey[i];
            if (v != 0ULL) {
                int a = (int)(0x3FFFFu - (unsigned)(v & 0x3FFFFULL));
                float4 b = g_boxes[a];
                if (sup_test(b.x, b.y, b.z, b.w, g_areas[a],
                             wb.x, wb.y, wb.z, wb.w, war))
                    g_skey[i] = 0ULL;
            }
        }
        nk3++;
        __syncthreads();
    }
    __syncthreads();

    // ---- final output: 32 warps cover 300 keeps ----
    for (int d = wrp; d < MAXDET; d += BLK3 / 32) {
        bool valid = d < nk3;
        float score = 0.f, clsid = -1.f;
        float bx0 = 0.f, bx1 = 0.f, bx2 = 0.f, bx3 = 0.f;
        if (valid) {
            int idx = g_keep[d];
            const float* row = cls + (size_t)idx * C;
            float best = -FLT_MAX;
            int bi = 0x7fffffff;
            for (int c = lane; c < C; c += 32) {
                float vv = row[c];
                if (vv > best) { best = vv; bi = c; }
            }
            #pragma unroll
            for (int off = 16; off; off >>= 1) {
                float ov = __shfl_down_sync(0xffffffffu, best, off);
                int   oi = __shfl_down_sync(0xffffffffu, bi,   off);
                if (ov > best || (ov == best && oi < bi)) { best = ov; bi = oi; }
            }
            best = __shfl_sync(0xffffffffu, best, 0);
            bi   = __shfl_sync(0xffffffffu, bi,   0);
            score = best;
            clsid = (float)bi;
            float4 b = g_kbox[d];
            bx0 = b.x; bx1 = b.y; bx2 = b.z; bx3 = b.w;
        }
        if (lane == 0) {
            out[d]                      = score;
            out[MAXDET + d]             = clsid;
            out[2 * MAXDET + 4 * d + 0] = bx0;
            out[2 * MAXDET + 4 * d + 1] = bx1;
            out[2 * MAXDET + 4 * d + 2] = bx2;
            out[2 * MAXDET + 4 * d + 3] = bx3;
            out[6 * MAXDET + d]         = valid ? 1.0f : 0.0f;
        }
    }
    __syncthreads();
    if (t == 0) g_cnt3 = 0;
}

// ---------------------------------------------------------------------------
extern "C" void kernel_launch(void* const* d_in, const int* in_sizes, int n_in,
                              void* d_out, int out_size)
{
    const float* cls = (const float*)d_in[0];
    const float* reg = (const float*)d_in[1];
    const float* anc = (const float*)d_in[2];
    const int*   ph  = (n_in > 3) ? (const int*)d_in[3] : nullptr;
    const int*   pw  = (n_in > 4) ? (const int*)d_in[4] : nullptr;

    int A = in_sizes[2] / 4;
    if (A > MAXA) A = MAXA;
    int C = in_sizes[0] / A;

    prep_rank_kernel<<<(A + TILE1 - 1) / TILE1, BLK1>>>(cls, reg, anc, ph, pw, A, C);
    pair_scan_kernel<<<PAIRB, BLK2>>>();
    flag_final_kernel<<<(A + BLK3 - 1) / BLK3, BLK3>>>(cls, A, C, (float*)d_out);
}

// round 14
// speedup vs baseline: 1.3001x; 1.3001x over previous
#include <cuda_runtime.h>
#include <cuda_bf16.h>
#include <cfloat>
#include <cstdint>

// ---------------------------------------------------------------------------
// RetinaNet postprocess, round 14: three kernels, all 256-thread blocks.
//   K1 prep        : (proven R6/R9 shape) class-max via SMEM atomicMax over
//                    64 anchors/block, decode+clip, slab emit (score>CUTOFF)
//   K2 rank+pair+scan (64 blocks):
//                    slice-rank (8 thr/item) -> 64-block nanosleep grid
//                    barrier -> upper-triangular IoU mask rows -> last block
//                    warp0: exact greedy with cp.async SMEM ring, early-exit
//                    at 300 keeps; resets counters
//   K3 flag+final  : (proven R8 flag shape) tail vs snapshot kept set;
//                    last block: serial reference greedy over survivors
//                    (normally none) + warp-per-keep argmax + output tuple
// Exactness: slab = {score > CUTOFF} is a clean cut in descending (score,idx)
// order; removed-mask greedy == reference greedy; kept set monotone; tail
// path exact for any cut; slab overflow (>T0) => slab treated empty =>
// everything flows through the exact serial tail path (slow but correct).
// ---------------------------------------------------------------------------

#define MAXA   262144
#define MAXDET 300
#define T0     2048
#define W0     32
#define NCH    8
#define PAIRB  64
#define BLK    256
#define PSTTHD 0.05f
#define CUTOFF 0.99990f
#define NMSTHD 0.5f

typedef unsigned long long ull;

__device__ float  g_keys [MAXA];
__device__ float4 g_boxes[MAXA];
__device__ float  g_areas[MAXA];
__device__ ull    g_ckeys[T0];
__device__ int    g_cidx [T0];
__device__ float4 g_cbox [T0];
__device__ float  g_carea[T0];
__device__ ull    g_mask [T0 * W0];
__device__ ull    g_skey [MAXA];
__device__ float4 g_kbox [MAXDET];
__device__ float  g_karea[MAXDET];
__device__ int    g_keep [MAXDET];
__device__ int    g_scnt;
__device__ int    g_nsurv;
__device__ int    g_nk;
__device__ int    g_overflow;
__device__ unsigned g_bar, g_cnt2, g_cnt3;

__device__ __forceinline__ bool sup_test(float x1, float y1, float x2, float y2, float ar,
                                         float X1, float Y1, float X2, float Y2, float AR)
{
    float xx1 = fmaxf(x1, X1);
    float yy1 = fmaxf(y1, Y1);
    float xx2 = fminf(x2, X2);
    float yy2 = fminf(y2, Y2);
    float inter = fmaxf(xx2 - xx1, 0.0f) * fmaxf(yy2 - yy1, 0.0f);
    float iou = inter / (ar + AR - inter + 1e-8f);
    return iou > NMSTHD;
}

__device__ __forceinline__ void cpa8(void* dst, const void* src)
{
    unsigned s = (unsigned)__cvta_generic_to_shared(dst);
    asm volatile("cp.async.ca.shared.global [%0], [%1], 8;" :: "r"(s), "l"(src) : "memory");
}
#define CPA_COMMIT()  asm volatile("cp.async.commit_group;" ::: "memory")
#define CPA_WAIT7()   asm volatile("cp.async.wait_group 7;" ::: "memory")
#define CPA_WAITALL() asm volatile("cp.async.wait_all;" ::: "memory")

// ===========================================================================
// K1: prep — 64 anchors per 256-thread block (the measured-fast shape).
// ===========================================================================
__global__ void __launch_bounds__(BLK)
prep_kernel(const float* __restrict__ cls,
            const float* __restrict__ reg,
            const float* __restrict__ anc,
            const int*   __restrict__ ph,
            const int*   __restrict__ pw,
            int A, int C)
{
    __shared__ unsigned srow[64];
    int t = threadIdx.x;
    int base = blockIdx.x * 64;
    if (t < 64) srow[t] = 0u;
    __syncthreads();

    if ((C & 3) == 0) {
        int f4r = C >> 2;
        int tot = 64 * f4r;
        const float4* cb = (const float4*)cls + (size_t)base * f4r;
        for (int i = t; i < tot; i += BLK) {
            int r = i / f4r;
            if (base + r < A) {
                float4 v = cb[i];
                float m = fmaxf(fmaxf(v.x, v.y), fmaxf(v.z, v.w));
                atomicMax(&srow[r], __float_as_uint(m));
            }
        }
    } else {
        for (int i = t; i < 64 * C; i += BLK) {
            int r = i / C;
            if (base + r < A) {
                float m = cls[(size_t)(base + r) * C + (i % C)];
                atomicMax(&srow[r], __float_as_uint(m));
            }
        }
    }
    __syncthreads();

    if (t < 64 && base + t < A) {
        int a = base + t;
        float m = __uint_as_float(srow[t]);
        g_keys[a] = (m > PSTTHD) ? m : 0.0f;
        if (m > CUTOFF) {
            int p = atomicAdd(&g_scnt, 1);
            if (p < T0)
                g_ckeys[p] = ((ull)__float_as_uint(m) << 18) |
                             (ull)(0x3FFFFu - (unsigned)a);
        }
        float4 an = ((const float4*)anc)[a];
        float4 rg = ((const float4*)reg)[a];
        float bw = an.z - an.x;
        float bh = an.w - an.y;
        float cx = an.x + 0.5f * bw;
        float cy = an.y + 0.5f * bh;
        float pcx = cx + (rg.x * 0.1f) * bw;
        float pcy = cy + (rg.y * 0.1f) * bh;
        float pw_ = expf(rg.z * 0.2f) * bw;
        float ph_ = expf(rg.w * 0.2f) * bh;
        float Wd = pw ? (float)__ldg(pw) : 1024.0f;
        float Hd = ph ? (float)__ldg(ph) : 1024.0f;
        float x1 = fmaxf(pcx - 0.5f * pw_, 0.0f);
        float y1 = fmaxf(pcy - 0.5f * ph_, 0.0f);
        float x2 = fminf(pcx + 0.5f * pw_, Wd);
        float y2 = fminf(pcy + 0.5f * ph_, Hd);
        g_boxes[a] = make_float4(x1, y1, x2, y2);
        g_areas[a] = (x2 - x1) * (y2 - y1);
    }
}

// ===========================================================================
// K2: rank (sliced) -> grid barrier -> pair -> last-block ring scan.
// 64 blocks x 256; all co-resident (64 << 148 SMs) so the barrier is safe.
// ===========================================================================
__global__ void __launch_bounds__(BLK)
rank_pair_scan_kernel()
{
    __shared__ union {
        struct { ull skeys[T0]; int sranks[64]; } r;          // rank (16.3 KB)
        struct { float4 scb[T0]; float sca[T0]; } p;          // pair (40 KB)
        struct { ull ring[NCH][16][32]; int spos[MAXDET]; } s;// scan (34 KB)
    } sm;
    __shared__ int is_last;
    int t = threadIdx.x;
    int lane = t & 31;
    int scnt = g_scnt;
    int overflow = (scnt > T0) ? 1 : 0;
    int n = overflow ? 0 : scnt;

    // ---- rank slice: this block ranks items [lo, hi); 8 threads per item ----
    if (n > 0) {
        for (int i = t; i < n; i += BLK) sm.r.skeys[i] = g_ckeys[i];
        if (t < 64) sm.r.sranks[t] = 0;
        __syncthreads();

        int per = (n + PAIRB - 1) / PAIRB;            // <= 32
        int lo = blockIdx.x * per;
        int item = t >> 3;                            // 0..31
        int sl   = t & 7;
        int i = lo + item;
        if (item < per && i < n) {
            ull mykey = sm.r.skeys[i];
            int jlo = (sl * n) >> 3;
            int jhi = ((sl + 1) * n) >> 3;
            int r = 0;
            for (int j = jlo; j < jhi; j++) r += (sm.r.skeys[j] > mykey) ? 1 : 0;
            atomicAdd(&sm.r.sranks[item], r);
        }
        __syncthreads();
        if (sl == 0 && item < per && i < n) {
            ull mykey = sm.r.skeys[i];
            int r = sm.r.sranks[item];
            int a = (int)(0x3FFFFu - (unsigned)(mykey & 0x3FFFFULL));
            g_cidx[r]  = a;
            g_cbox[r]  = g_boxes[a];
            g_carea[r] = g_areas[a];
        }
    }

    // ---- grid barrier over the 64 blocks (nanosleep backoff) ----
    __threadfence();
    __syncthreads();
    if (t == 0) {
        atomicAdd(&g_bar, 1u);
        while (*((volatile unsigned*)&g_bar) < PAIRB)
            __nanosleep(128);
    }
    __syncthreads();

    // ---- pair: upper-triangular masks ----
    if (n > 0) {
        for (int i = t; i < n; i += BLK) {
            sm.p.scb[i] = g_cbox[i];
            sm.p.sca[i] = g_carea[i];
        }
        __syncthreads();
        int items = n * W0;
        for (int it = blockIdx.x * BLK + t; it < items; it += PAIRB * BLK) {
            int i = it >> 5;
            int w = it & 31;
            int jbase = w << 6;
            int jstart = max(jbase, i + 1);
            int jend   = min(jbase + 64, n);
            ull word = 0ULL;
            if (jstart < jend) {
                float4 bi = sm.p.scb[i];
                float  ai = sm.p.sca[i];
                for (int j = jstart; j < jend; j++) {
                    float4 bj = sm.p.scb[j];
                    if (sup_test(bi.x, bi.y, bi.z, bi.w, ai,
                                 bj.x, bj.y, bj.z, bj.w, sm.p.sca[j]))
                        word |= 1ULL << (j - jbase);
                }
            }
            g_mask[it] = word;
        }
    }

    // ---- epilogue: last block's warp0 runs the exact greedy scan ----
    __threadfence();
    __syncthreads();
    if (t == 0) {
        unsigned old = atomicAdd(&g_cnt2, 1u);
        is_last = (old == PAIRB - 1u) ? 1 : 0;
    }
    __syncthreads();
    if (!is_last) return;
    __threadfence();
    __syncthreads();

    if (t < 32) {
        int nchunks = (n + 15) >> 4;
        for (int c = 0; c < NCH; c++) {
            int cb = c << 4;
            #pragma unroll
            for (int r = 0; r < 16; r++) {
                int i = cb + r;
                if (i < n) cpa8(&sm.s.ring[c][r][lane], &g_mask[(size_t)i * W0 + lane]);
            }
            CPA_COMMIT();
        }
        ull removed = 0ULL;
        int nk = 0;
        for (int c = 0; c < nchunks && nk < MAXDET; c++) {
            CPA_WAIT7();
            __syncwarp();
            int slot = c & (NCH - 1);
            int cb = c << 4;
            ull buf[16];
            #pragma unroll
            for (int r = 0; r < 16; r++) buf[r] = sm.s.ring[slot][r][lane];

            int lim = min(16, n - cb);
            int widx = cb >> 6;
            ull dec = 0ULL;
            if (lane == widx) {
                ull w = removed;
                for (int r = 0; r < lim; r++) {
                    int bit = (cb + r) & 63;
                    if (!((w >> bit) & 1ULL)) {
                        dec |= 1ULL << r;
                        w |= buf[r];
                    }
                }
                removed = w;
            }
            dec = __shfl_sync(0xffffffffu, dec, widx);
            while (dec) {
                int r = __ffsll(dec) - 1;
                dec &= dec - 1;
                removed |= buf[r];
                if (lane == 0) sm.s.spos[nk] = cb + r;
                nk++;
                if (nk >= MAXDET) break;
            }

            int pb = (c + NCH) << 4;
            #pragma unroll
            for (int r = 0; r < 16; r++) {
                int i = pb + r;
                if (i < n) cpa8(&sm.s.ring[slot][r][lane], &g_mask[(size_t)i * W0 + lane]);
            }
            CPA_COMMIT();
        }
        CPA_WAITALL();
        __syncwarp();
        for (int k = lane; k < nk; k += 32) {
            int p = sm.s.spos[k];
            g_keep[k]  = g_cidx[p];
            g_kbox[k]  = g_cbox[p];
            g_karea[k] = g_carea[p];
        }
        if (lane == 0) {
            g_nk = nk;
            g_overflow = overflow;
            g_scnt = 0;                    // next replay starts clean
            g_nsurv = 0;
            g_cnt2 = 0;
            g_bar = 0;
        }
    }
}

// ===========================================================================
// K3: flag (grid, 256-thread blocks) + last block: serial tail + final.
// ===========================================================================
__global__ void __launch_bounds__(BLK)
flag_final_kernel(const float* __restrict__ cls, int A, int C,
                  float* __restrict__ out)
{
    __shared__ float4 skb[MAXDET];
    __shared__ float  ska[MAXDET];
    __shared__ ull    sb[BLK];
    __shared__ float4 swin;
    __shared__ float  swar;
    __shared__ int    is_last;
    int t = threadIdx.x;
    int lane = t & 31;
    int wrp = t >> 5;

    // ---- flag: tail vs snapshot kept set ----
    int nk = g_nk;
    if (nk < MAXDET) {
        for (int k = t; k < nk; k += BLK) {
            skb[k] = g_kbox[k];
            ska[k] = g_karea[k];
        }
        __syncthreads();
        int sovf = g_overflow;
        int a = blockIdx.x * BLK + t;
        if (a < A) {
            float key = g_keys[a];
            if (key > PSTTHD && (sovf || !(key > CUTOFF))) {
                float4 b = g_boxes[a];
                float ar = g_areas[a];
                bool sup = false;
                for (int k = 0; k < nk; k++) {
                    if (sup_test(b.x, b.y, b.z, b.w, ar,
                                 skb[k].x, skb[k].y, skb[k].z, skb[k].w, ska[k])) {
                        sup = true;
                        break;
                    }
                }
                if (!sup) {
                    int p = atomicAdd(&g_nsurv, 1);
                    g_skey[p] = ((ull)__float_as_uint(key) << 18) |
                                (ull)(0x3FFFFu - (unsigned)a);
                }
            }
        }
    }

    // ---- epilogue selection ----
    __threadfence();
    __syncthreads();
    if (t == 0) {
        unsigned old = atomicAdd(&g_cnt3, 1u);
        is_last = (old == gridDim.x - 1u) ? 1 : 0;
    }
    __syncthreads();
    if (!is_last) return;
    __threadfence();

    // ---- serial reference greedy over survivors (normally none) ----
    int nk3 = g_nk;
    int ns = g_nsurv;
    while (nk3 < MAXDET && ns > 0) {
        ull best = 0ULL;
        for (int i = t; i < ns; i += BLK) {
            ull v = g_skey[i];
            if (v > best) best = v;
        }
        sb[t] = best;
        __syncthreads();
        for (int off = BLK / 2; off; off >>= 1) {
            if (t < off && sb[t + off] > sb[t]) sb[t] = sb[t + off];
            __syncthreads();
        }
        if (sb[0] == 0ULL) break;

        if (t == 0) {
            int a = (int)(0x3FFFFu - (unsigned)(sb[0] & 0x3FFFFULL));
            float4 b = g_boxes[a];
            float ar = g_areas[a];
            g_keep[nk3]  = a;
            g_kbox[nk3]  = b;
            g_karea[nk3] = ar;
            swin = b;
            swar = ar;
        }
        __syncthreads();
        float4 wb = swin;
        float war = swar;
        for (int i = t; i < ns; i += BLK) {
            ull v = g_skey[i];
            if (v != 0ULL) {
                int a = (int)(0x3FFFFu - (unsigned)(v & 0x3FFFFULL));
                float4 b = g_boxes[a];
                if (sup_test(b.x, b.y, b.z, b.w, g_areas[a],
                             wb.x, wb.y, wb.z, wb.w, war))
                    g_skey[i] = 0ULL;
            }
        }
        nk3++;
        __syncthreads();
    }
    __syncthreads();

    // ---- final output: 8 warps cover 300 keeps ----
    for (int d = wrp; d < MAXDET; d += BLK / 32) {
        bool valid = d < nk3;
        float score = 0.f, clsid = -1.f;
        float bx0 = 0.f, bx1 = 0.f, bx2 = 0.f, bx3 = 0.f;
        if (valid) {
            int idx = g_keep[d];
            const float* row = cls + (size_t)idx * C;
            float best = -FLT_MAX;
            int bi = 0x7fffffff;
            for (int c = lane; c < C; c += 32) {
                float vv = row[c];
                if (vv > best) { best = vv; bi = c; }
            }
            #pragma unroll
            for (int off = 16; off; off >>= 1) {
                float ov = __shfl_down_sync(0xffffffffu, best, off);
                int   oi = __shfl_down_sync(0xffffffffu, bi,   off);
                if (ov > best || (ov == best && oi < bi)) { best = ov; bi = oi; }
            }
            best = __shfl_sync(0xffffffffu, best, 0);
            bi   = __shfl_sync(0xffffffffu, bi,   0);
            score = best;
            clsid = (float)bi;
            float4 b = g_kbox[d];
            bx0 = b.x; bx1 = b.y; bx2 = b.z; bx3 = b.w;
        }
        if (lane == 0) {
            out[d]                      = score;
            out[MAXDET + d]             = clsid;
            out[2 * MAXDET + 4 * d + 0] = bx0;
            out[2 * MAXDET + 4 * d + 1] = bx1;
            out[2 * MAXDET + 4 * d + 2] = bx2;
            out[2 * MAXDET + 4 * d + 3] = bx3;
            out[6 * MAXDET + d]         = valid ? 1.0f : 0.0f;
        }
    }
    __syncthreads();
    if (t == 0) g_cnt3 = 0;
}

// ---------------------------------------------------------------------------
extern "C" void kernel_launch(void* const* d_in, const int* in_sizes, int n_in,
                              void* d_out, int out_size)
{
    const float* cls = (const float*)d_in[0];
    const float* reg = (const float*)d_in[1];
    const float* anc = (const float*)d_in[2];
    const int*   ph  = (n_in > 3) ? (const int*)d_in[3] : nullptr;
    const int*   pw  = (n_in > 4) ? (const int*)d_in[4] : nullptr;

    int A = in_sizes[2] / 4;
    if (A > MAXA) A = MAXA;
    int C = in_sizes[0] / A;

    prep_kernel<<<(A + 63) / 64, BLK>>>(cls, reg, anc, ph, pw, A, C);
    rank_pair_scan_kernel<<<PAIRB, BLK>>>();
    flag_final_kernel<<<(A + BLK - 1) / BLK, BLK>>>(cls, A, C, (float*)d_out);
}

// round 15
// speedup vs baseline: 1.8214x; 1.4009x over previous
#include <cuda_runtime.h>
#include <cuda_bf16.h>
#include <cfloat>
#include <cstdint>

// ---------------------------------------------------------------------------
// RetinaNet postprocess, round 15: three kernels, 256-thread blocks.
//   K1 prep : class-max via 4-threads/row ownership (1 atomicMax/thread),
//             decode+clip, slab emit (score > CUTOFF)
//   K2 rank+pair+scan (64 blocks, 132 KB dynamic SMEM):
//             sliced comparison-rank -> nanosleep grid barrier -> upper-tri
//             IoU mask rows (W0=16) -> last block stages masks into SMEM and
//             warp0 runs the exact greedy scan pure-LDS; resets counters
//   K3 flag+final : tail vs snapshot kept set; last block: serial reference
//             greedy over survivors + warp-per-keep argmax + output tuple
// Exactness: slab = {score > CUTOFF} is a clean cut in descending (score,idx)
// order; removed-mask greedy == reference greedy; kept set monotone; tail
// path exact for any cut; slab overflow (>T0) => slab treated empty =>
// everything flows through the exact serial tail path (slow but correct).
// ---------------------------------------------------------------------------

#define MAXA   262144
#define MAXDET 300
#define T0     1024
#define W0     16
#define PAIRB  64
#define BLK    256
#define PSTTHD 0.05f
#define CUTOFF 0.99995f
#define NMSTHD 0.5f
#define DSMEM  (T0 * W0 * 8)       // 128 KB mask stage (largest union member)

typedef unsigned long long ull;

__device__ float  g_keys [MAXA];
__device__ float4 g_boxes[MAXA];
__device__ float  g_areas[MAXA];
__device__ ull    g_ckeys[T0];
__device__ int    g_cidx [T0];
__device__ float4 g_cbox [T0];
__device__ float  g_carea[T0];
__device__ ull    g_mask [T0 * W0];
__device__ ull    g_skey [MAXA];
__device__ float4 g_kbox [MAXDET];
__device__ float  g_karea[MAXDET];
__device__ int    g_keep [MAXDET];
__device__ int    g_scnt;
__device__ int    g_nsurv;
__device__ int    g_nk;
__device__ int    g_overflow;
__device__ unsigned g_bar, g_cnt2, g_cnt3;

__device__ __forceinline__ bool sup_test(float x1, float y1, float x2, float y2, float ar,
                                         float X1, float Y1, float X2, float Y2, float AR)
{
    float xx1 = fmaxf(x1, X1);
    float yy1 = fmaxf(y1, Y1);
    float xx2 = fminf(x2, X2);
    float yy2 = fminf(y2, Y2);
    float inter = fmaxf(xx2 - xx1, 0.0f) * fmaxf(yy2 - yy1, 0.0f);
    float iou = inter / (ar + AR - inter + 1e-8f);
    return iou > NMSTHD;
}

// ===========================================================================
// K1: prep — 64 anchors / 256-thread block; 4 threads own one row each
// (5 float4 private max, one SMEM atomicMax per thread), then decode.
// ===========================================================================
__global__ void __launch_bounds__(BLK)
prep_kernel(const float* __restrict__ cls,
            const float* __restrict__ reg,
            const float* __restrict__ anc,
            const int*   __restrict__ ph,
            const int*   __restrict__ pw,
            int A, int C)
{
    __shared__ unsigned srow[64];
    int t = threadIdx.x;
    int base = blockIdx.x * 64;
    if (t < 64) srow[t] = 0u;
    __syncthreads();

    if ((C & 3) == 0) {
        int f4r = C >> 2;                       // 20 for C=80
        int row  = t >> 2;                      // 4 threads per row
        int part = t & 3;
        if (base + row < A) {
            const float4* rp = (const float4*)cls + (size_t)(base + row) * f4r;
            float m = -FLT_MAX;
            for (int j = part; j < f4r; j += 4) {
                float4 v = rp[j];
                m = fmaxf(m, fmaxf(fmaxf(v.x, v.y), fmaxf(v.z, v.w)));
            }
            atomicMax(&srow[row], __float_as_uint(m));
        }
    } else {
        for (int i = t; i < 64 * C; i += BLK) {
            int r = i / C;
            if (base + r < A) {
                float m = cls[(size_t)(base + r) * C + (i % C)];
                atomicMax(&srow[r], __float_as_uint(m));
            }
        }
    }
    __syncthreads();

    if (t < 64 && base + t < A) {
        int a = base + t;
        float m = __uint_as_float(srow[t]);
        g_keys[a] = (m > PSTTHD) ? m : 0.0f;
        if (m > CUTOFF) {
            int p = atomicAdd(&g_scnt, 1);
            if (p < T0)
                g_ckeys[p] = ((ull)__float_as_uint(m) << 18) |
                             (ull)(0x3FFFFu - (unsigned)a);
        }
        float4 an = ((const float4*)anc)[a];
        float4 rg = ((const float4*)reg)[a];
        float bw = an.z - an.x;
        float bh = an.w - an.y;
        float cx = an.x + 0.5f * bw;
        float cy = an.y + 0.5f * bh;
        float pcx = cx + (rg.x * 0.1f) * bw;
        float pcy = cy + (rg.y * 0.1f) * bh;
        float pw_ = expf(rg.z * 0.2f) * bw;
        float ph_ = expf(rg.w * 0.2f) * bh;
        float Wd = pw ? (float)__ldg(pw) : 1024.0f;
        float Hd = ph ? (float)__ldg(ph) : 1024.0f;
        float x1 = fmaxf(pcx - 0.5f * pw_, 0.0f);
        float y1 = fmaxf(pcy - 0.5f * ph_, 0.0f);
        float x2 = fminf(pcx + 0.5f * pw_, Wd);
        float y2 = fminf(pcy + 0.5f * ph_, Hd);
        g_boxes[a] = make_float4(x1, y1, x2, y2);
        g_areas[a] = (x2 - x1) * (y2 - y1);
    }
}

// ===========================================================================
// K2: rank -> barrier -> pair -> last block stages masks to SMEM + scans.
// 64 blocks x 256, 132 KB dynamic SMEM (so 1 block/SM; 64 << 148 co-resident).
// ===========================================================================
__global__ void __launch_bounds__(BLK)
rank_pair_scan_kernel()
{
    extern __shared__ char dyn[];
    __shared__ int sranks[64];
    __shared__ int spos[MAXDET];
    __shared__ int is_last;

    int t = threadIdx.x;
    int lane = t & 31;
    int scnt = g_scnt;
    int overflow = (scnt > T0) ? 1 : 0;
    int n = overflow ? 0 : scnt;

    // ---- rank slice: 8 threads per item, 32 items per block ----
    if (n > 0) {
        ull* skeys = (ull*)dyn;
        for (int i = t; i < n; i += BLK) skeys[i] = g_ckeys[i];
        if (t < 64) sranks[t] = 0;
        __syncthreads();

        int per = (n + PAIRB - 1) / PAIRB;    // <= 16 for n <= 1024
        int lo = blockIdx.x * per;
        int item = t >> 3;
        int sl   = t & 7;
        int i = lo + item;
        if (item < per && i < n) {
            ull mykey = skeys[i];
            int jlo = (sl * n) >> 3;
            int jhi = ((sl + 1) * n) >> 3;
            int r = 0;
            for (int j = jlo; j < jhi; j++) r += (skeys[j] > mykey) ? 1 : 0;
            atomicAdd(&sranks[item], r);
        }
        __syncthreads();
        if (sl == 0 && item < per && i < n) {
            ull mykey = skeys[i];
            int r = sranks[item];
            int a = (int)(0x3FFFFu - (unsigned)(mykey & 0x3FFFFULL));
            g_cidx[r]  = a;
            g_cbox[r]  = g_boxes[a];
            g_carea[r] = g_areas[a];
        }
    }

    // ---- grid barrier over 64 co-resident blocks (nanosleep backoff) ----
    __threadfence();
    __syncthreads();
    if (t == 0) {
        atomicAdd(&g_bar, 1u);
        while (*((volatile unsigned*)&g_bar) < PAIRB)
            __nanosleep(128);
    }
    __syncthreads();

    // ---- pair: upper-triangular masks (W0=16 words per row) ----
    if (n > 0) {
        float4* scb = (float4*)dyn;
        float*  sca = (float*)(dyn + T0 * sizeof(float4));
        for (int i = t; i < n; i += BLK) {
            scb[i] = g_cbox[i];
            sca[i] = g_carea[i];
        }
        __syncthreads();
        int items = n * W0;
        for (int it = blockIdx.x * BLK + t; it < items; it += PAIRB * BLK) {
            int i = it >> 4;
            int w = it & 15;
            int jbase = w << 6;
            int jstart = max(jbase, i + 1);
            int jend   = min(jbase + 64, n);
            ull word = 0ULL;
            if (jstart < jend) {
                float4 bi = scb[i];
                float  ai = sca[i];
                for (int j = jstart; j < jend; j++) {
                    float4 bj = scb[j];
                    if (sup_test(bi.x, bi.y, bi.z, bi.w, ai,
                                 bj.x, bj.y, bj.z, bj.w, sca[j]))
                        word |= 1ULL << (j - jbase);
                }
            }
            g_mask[it] = word;
        }
    }

    // ---- epilogue: last block stages masks into SMEM, warp0 scans ----
    __threadfence();
    __syncthreads();
    if (t == 0) {
        unsigned old = atomicAdd(&g_cnt2, 1u);
        is_last = (old == PAIRB - 1u) ? 1 : 0;
    }
    __syncthreads();
    if (!is_last) return;
    __threadfence();
    __syncthreads();

    ull* smask = (ull*)dyn;
    int nwords = n * W0;
    for (int i = t; i < nwords; i += BLK) smask[i] = g_mask[i];
    __syncthreads();

    if (t < 32) {
        ull removed = 0ULL;
        int nk = 0;
        int nchunks = (n + 15) >> 4;
        for (int c = 0; c < nchunks && nk < MAXDET; c++) {
            int cb = c << 4;
            ull buf[16];
            #pragma unroll
            for (int r = 0; r < 16; r++) {
                int i = cb + r;
                buf[r] = (lane < W0 && i < n) ? smask[i * W0 + lane] : 0ULL;
            }
            int lim = min(16, n - cb);
            int widx = cb >> 6;                  // same word for all 16 rows
            ull dec = 0ULL;
            if (lane == widx) {
                ull w = removed;
                for (int r = 0; r < lim; r++) {
                    int bit = (cb + r) & 63;
                    if (!((w >> bit) & 1ULL)) {
                        dec |= 1ULL << r;
                        w |= buf[r];
                    }
                }
                removed = w;
            }
            dec = __shfl_sync(0xffffffffu, dec, widx);
            while (dec) {
                int r = __ffsll(dec) - 1;
                dec &= dec - 1;
                removed |= buf[r];
                if (lane == 0) spos[nk] = cb + r;
                nk++;
                if (nk >= MAXDET) break;
            }
        }
        __syncwarp();
        for (int k = lane; k < nk; k += 32) {
            int p = spos[k];
            g_keep[k]  = g_cidx[p];
            g_kbox[k]  = g_cbox[p];
            g_karea[k] = g_carea[p];
        }
        if (lane == 0) {
            g_nk = nk;
            g_overflow = overflow;
            g_scnt = 0;                          // next replay starts clean
            g_nsurv = 0;
            g_cnt2 = 0;
            g_bar = 0;
        }
    }
}

// ===========================================================================
// K3: flag (grid) + last block: serial tail + final output.
// ===========================================================================
__global__ void __launch_bounds__(BLK)
flag_final_kernel(const float* __restrict__ cls, int A, int C,
                  float* __restrict__ out)
{
    __shared__ float4 skb[MAXDET];
    __shared__ float  ska[MAXDET];
    __shared__ ull    sb[BLK];
    __shared__ float4 swin;
    __shared__ float  swar;
    __shared__ int    is_last;
    int t = threadIdx.x;
    int lane = t & 31;
    int wrp = t >> 5;

    // ---- flag: tail vs snapshot kept set ----
    int nk = g_nk;
    if (nk < MAXDET) {
        for (int k = t; k < nk; k += BLK) {
            skb[k] = g_kbox[k];
            ska[k] = g_karea[k];
        }
        __syncthreads();
        int sovf = g_overflow;
        int a = blockIdx.x * BLK + t;
        if (a < A) {
            float key = g_keys[a];
            if (key > PSTTHD && (sovf || !(key > CUTOFF))) {
                float4 b = g_boxes[a];
                float ar = g_areas[a];
                bool sup = false;
                for (int k = 0; k < nk; k++) {
                    if (sup_test(b.x, b.y, b.z, b.w, ar,
                                 skb[k].x, skb[k].y, skb[k].z, skb[k].w, ska[k])) {
                        sup = true;
                        break;
                    }
                }
                if (!sup) {
                    int p = atomicAdd(&g_nsurv, 1);
                    g_skey[p] = ((ull)__float_as_uint(key) << 18) |
                                (ull)(0x3FFFFu - (unsigned)a);
                }
            }
        }
    }

    // ---- epilogue selection ----
    __threadfence();
    __syncthreads();
    if (t == 0) {
        unsigned old = atomicAdd(&g_cnt3, 1u);
        is_last = (old == gridDim.x - 1u) ? 1 : 0;
    }
    __syncthreads();
    if (!is_last) return;
    __threadfence();

    // ---- serial reference greedy over survivors ----
    int nk3 = g_nk;
    int ns = g_nsurv;
    while (nk3 < MAXDET && ns > 0) {
        ull best = 0ULL;
        for (int i = t; i < ns; i += BLK) {
            ull v = g_skey[i];
            if (v > best) best = v;
        }
        sb[t] = best;
        __syncthreads();
        for (int off = BLK / 2; off; off >>= 1) {
            if (t < off && sb[t + off] > sb[t]) sb[t] = sb[t + off];
            __syncthreads();
        }
        if (sb[0] == 0ULL) break;

        if (t == 0) {
            int a = (int)(0x3FFFFu - (unsigned)(sb[0] & 0x3FFFFULL));
            float4 b = g_boxes[a];
            float ar = g_areas[a];
            g_keep[nk3]  = a;
            g_kbox[nk3]  = b;
            g_karea[nk3] = ar;
            swin = b;
            swar = ar;
        }
        __syncthreads();
        float4 wb = swin;
        float war = swar;
        for (int i = t; i < ns; i += BLK) {
            ull v = g_skey[i];
            if (v != 0ULL) {
                int a = (int)(0x3FFFFu - (unsigned)(v & 0x3FFFFULL));
                float4 b = g_boxes[a];
                if (sup_test(b.x, b.y, b.z, b.w, g_areas[a],
                             wb.x, wb.y, wb.z, wb.w, war))
                    g_skey[i] = 0ULL;
            }
        }
        nk3++;
        __syncthreads();
    }
    __syncthreads();

    // ---- final output: 8 warps cover 300 keeps ----
    for (int d = wrp; d < MAXDET; d += BLK / 32) {
        bool valid = d < nk3;
        float score = 0.f, clsid = -1.f;
        float bx0 = 0.f, bx1 = 0.f, bx2 = 0.f, bx3 = 0.f;
        if (valid) {
            int idx = g_keep[d];
            const float* row = cls + (size_t)idx * C;
            float best = -FLT_MAX;
            int bi = 0x7fffffff;
            for (int c = lane; c < C; c += 32) {
                float vv = row[c];
                if (vv > best) { best = vv; bi = c; }
            }
            #pragma unroll
            for (int off = 16; off; off >>= 1) {
                float ov = __shfl_down_sync(0xffffffffu, best, off);
                int   oi = __shfl_down_sync(0xffffffffu, bi,   off);
                if (ov > best || (ov == best && oi < bi)) { best = ov; bi = oi; }
            }
            best = __shfl_sync(0xffffffffu, best, 0);
            bi   = __shfl_sync(0xffffffffu, bi,   0);
            score = best;
            clsid = (float)bi;
            float4 b = g_kbox[d];
            bx0 = b.x; bx1 = b.y; bx2 = b.z; bx3 = b.w;
        }
        if (lane == 0) {
            out[d]                      = score;
            out[MAXDET + d]             = clsid;
            out[2 * MAXDET + 4 * d + 0] = bx0;
            out[2 * MAXDET + 4 * d + 1] = bx1;
            out[2 * MAXDET + 4 * d + 2] = bx2;
            out[2 * MAXDET + 4 * d + 3] = bx3;
            out[6 * MAXDET + d]         = valid ? 1.0f : 0.0f;
        }
    }
    __syncthreads();
    if (t == 0) g_cnt3 = 0;
}

// ---------------------------------------------------------------------------
extern "C" void kernel_launch(void* const* d_in, const int* in_sizes, int n_in,
                              void* d_out, int out_size)
{
    const float* cls = (const float*)d_in[0];
    const float* reg = (const float*)d_in[1];
    const float* anc = (const float*)d_in[2];
    const int*   ph  = (n_in > 3) ? (const int*)d_in[3] : nullptr;
    const int*   pw  = (n_in > 4) ? (const int*)d_in[4] : nullptr;

    int A = in_sizes[2] / 4;
    if (A > MAXA) A = MAXA;
    int C = in_sizes[0] / A;

    static int configured = 0;
    if (!configured) {
        cudaFuncSetAttribute(rank_pair_scan_kernel,
                             cudaFuncAttributeMaxDynamicSharedMemorySize, DSMEM);
        configured = 1;
    }

    prep_kernel<<<(A + 63) / 64, BLK>>>(cls, reg, anc, ph, pw, A, C);
    rank_pair_scan_kernel<<<PAIRB, BLK, DSMEM>>>();
    flag_final_kernel<<<(A + BLK - 1) / BLK, BLK>>>(cls, A, C, (float*)d_out);
}

// round 16
// speedup vs baseline: 2.2795x; 1.2515x over previous
#include <cuda_runtime.h>
#include <cuda_bf16.h>
#include <cfloat>
#include <cstdint>

// ---------------------------------------------------------------------------
// RetinaNet postprocess, round 16.
//   K1 prep (256-thr blocks): class-max via 4-threads/row (1 atomicMax/thr),
//             decode+clip, slab emit (score > CUTOFF)
//   K2 rank+pair+scan (64 blocks x 256, 132 KB dyn SMEM):
//             sliced comparison-rank -> nanosleep grid barrier -> upper-tri
//             IoU mask rows (W0=16) -> last block stages masks into SMEM and
//             warp0 runs the exact greedy pure-LDS; resets counters
//   K3 flag+final (1024-thr blocks): tail vs snapshot kept set, survivors
//             stored as COMPACT (key, box, area) records; last block: serial
//             reference greedy over compact survivors + warp-per-keep argmax
//             + output tuple
// Exactness: slab = {score > CUTOFF} is a clean cut in descending (score,idx)
// order; removed-mask greedy == reference greedy; kept set monotone; tail
// path exact for any cut; slab overflow (>T0) => slab treated empty =>
// everything flows through the exact serial tail path (slow but correct).
// ---------------------------------------------------------------------------

#define MAXA   262144
#define MAXDET 300
#define T0     1024
#define W0     16
#define PAIRB  64
#define BLK    256
#define BLK3   1024
#define PSTTHD 0.05f
#define CUTOFF 0.99995f
#define NMSTHD 0.5f
#define DSMEM  (T0 * W0 * 8)       // 128 KB mask stage (largest K2 phase)

typedef unsigned long long ull;

__device__ float  g_keys [MAXA];
__device__ float4 g_boxes[MAXA];
__device__ float  g_areas[MAXA];
__device__ ull    g_ckeys[T0];
__device__ int    g_cidx [T0];
__device__ float4 g_cbox [T0];
__device__ float  g_carea[T0];
__device__ ull    g_mask [T0 * W0];
__device__ ull    g_skey [MAXA];    // compact survivor keys
__device__ float4 g_sbox [MAXA];    // compact survivor boxes
__device__ float  g_sarea[MAXA];    // compact survivor areas
__device__ float4 g_kbox [MAXDET];
__device__ float  g_karea[MAXDET];
__device__ int    g_keep [MAXDET];
__device__ int    g_scnt;
__device__ int    g_nsurv;
__device__ int    g_nk;
__device__ int    g_overflow;
__device__ unsigned g_bar, g_cnt2, g_cnt3;

__device__ __forceinline__ bool sup_test(float x1, float y1, float x2, float y2, float ar,
                                         float X1, float Y1, float X2, float Y2, float AR)
{
    float xx1 = fmaxf(x1, X1);
    float yy1 = fmaxf(y1, Y1);
    float xx2 = fminf(x2, X2);
    float yy2 = fminf(y2, Y2);
    float inter = fmaxf(xx2 - xx1, 0.0f) * fmaxf(yy2 - yy1, 0.0f);
    float iou = inter / (ar + AR - inter + 1e-8f);
    return iou > NMSTHD;
}

// ===========================================================================
// K1: prep — 64 anchors / 256-thread block; 4 threads own one row each.
// ===========================================================================
__global__ void __launch_bounds__(BLK)
prep_kernel(const float* __restrict__ cls,
            const float* __restrict__ reg,
            const float* __restrict__ anc,
            const int*   __restrict__ ph,
            const int*   __restrict__ pw,
            int A, int C)
{
    __shared__ unsigned srow[64];
    int t = threadIdx.x;
    int base = blockIdx.x * 64;
    if (t < 64) srow[t] = 0u;
    __syncthreads();

    if ((C & 3) == 0) {
        int f4r = C >> 2;
        int row  = t >> 2;
        int part = t & 3;
        if (base + row < A) {
            const float4* rp = (const float4*)cls + (size_t)(base + row) * f4r;
            float m = -FLT_MAX;
            for (int j = part; j < f4r; j += 4) {
                float4 v = rp[j];
                m = fmaxf(m, fmaxf(fmaxf(v.x, v.y), fmaxf(v.z, v.w)));
            }
            atomicMax(&srow[row], __float_as_uint(m));
        }
    } else {
        for (int i = t; i < 64 * C; i += BLK) {
            int r = i / C;
            if (base + r < A) {
                float m = cls[(size_t)(base + r) * C + (i % C)];
                atomicMax(&srow[r], __float_as_uint(m));
            }
        }
    }
    __syncthreads();

    if (t < 64 && base + t < A) {
        int a = base + t;
        float m = __uint_as_float(srow[t]);
        g_keys[a] = (m > PSTTHD) ? m : 0.0f;
        if (m > CUTOFF) {
            int p = atomicAdd(&g_scnt, 1);
            if (p < T0)
                g_ckeys[p] = ((ull)__float_as_uint(m) << 18) |
                             (ull)(0x3FFFFu - (unsigned)a);
        }
        float4 an = ((const float4*)anc)[a];
        float4 rg = ((const float4*)reg)[a];
        float bw = an.z - an.x;
        float bh = an.w - an.y;
        float cx = an.x + 0.5f * bw;
        float cy = an.y + 0.5f * bh;
        float pcx = cx + (rg.x * 0.1f) * bw;
        float pcy = cy + (rg.y * 0.1f) * bh;
        float pw_ = expf(rg.z * 0.2f) * bw;
        float ph_ = expf(rg.w * 0.2f) * bh;
        float Wd = pw ? (float)__ldg(pw) : 1024.0f;
        float Hd = ph ? (float)__ldg(ph) : 1024.0f;
        float x1 = fmaxf(pcx - 0.5f * pw_, 0.0f);
        float y1 = fmaxf(pcy - 0.5f * ph_, 0.0f);
        float x2 = fminf(pcx + 0.5f * pw_, Wd);
        float y2 = fminf(pcy + 0.5f * ph_, Hd);
        g_boxes[a] = make_float4(x1, y1, x2, y2);
        g_areas[a] = (x2 - x1) * (y2 - y1);
    }
}

// ===========================================================================
// K2: rank -> barrier -> pair -> last block stages masks to SMEM + scans.
// ===========================================================================
__global__ void __launch_bounds__(BLK)
rank_pair_scan_kernel()
{
    extern __shared__ char dyn[];
    __shared__ int sranks[64];
    __shared__ int spos[MAXDET];
    __shared__ int is_last;

    int t = threadIdx.x;
    int lane = t & 31;
    int scnt = g_scnt;
    int overflow = (scnt > T0) ? 1 : 0;
    int n = overflow ? 0 : scnt;

    // ---- rank slice: 8 threads per item ----
    if (n > 0) {
        ull* skeys = (ull*)dyn;
        for (int i = t; i < n; i += BLK) skeys[i] = g_ckeys[i];
        if (t < 64) sranks[t] = 0;
        __syncthreads();

        int per = (n + PAIRB - 1) / PAIRB;
        int lo = blockIdx.x * per;
        int item = t >> 3;
        int sl   = t & 7;
        int i = lo + item;
        if (item < per && i < n) {
            ull mykey = skeys[i];
            int jlo = (sl * n) >> 3;
            int jhi = ((sl + 1) * n) >> 3;
            int r = 0;
            for (int j = jlo; j < jhi; j++) r += (skeys[j] > mykey) ? 1 : 0;
            atomicAdd(&sranks[item], r);
        }
        __syncthreads();
        if (sl == 0 && item < per && i < n) {
            ull mykey = skeys[i];
            int r = sranks[item];
            int a = (int)(0x3FFFFu - (unsigned)(mykey & 0x3FFFFULL));
            g_cidx[r]  = a;
            g_cbox[r]  = g_boxes[a];
            g_carea[r] = g_areas[a];
        }
    }

    // ---- grid barrier over 64 co-resident blocks ----
    __threadfence();
    __syncthreads();
    if (t == 0) {
        atomicAdd(&g_bar, 1u);
        while (*((volatile unsigned*)&g_bar) < PAIRB)
            __nanosleep(128);
    }
    __syncthreads();

    // ---- pair: upper-triangular masks (W0=16) ----
    if (n > 0) {
        float4* scb = (float4*)dyn;
        float*  sca = (float*)(dyn + T0 * sizeof(float4));
        for (int i = t; i < n; i += BLK) {
            scb[i] = g_cbox[i];
            sca[i] = g_carea[i];
        }
        __syncthreads();
        int items = n * W0;
        for (int it = blockIdx.x * BLK + t; it < items; it += PAIRB * BLK) {
            int i = it >> 4;
            int w = it & 15;
            int jbase = w << 6;
            int jstart = max(jbase, i + 1);
            int jend   = min(jbase + 64, n);
            ull word = 0ULL;
            if (jstart < jend) {
                float4 bi = scb[i];
                float  ai = sca[i];
                for (int j = jstart; j < jend; j++) {
                    float4 bj = scb[j];
                    if (sup_test(bi.x, bi.y, bi.z, bi.w, ai,
                                 bj.x, bj.y, bj.z, bj.w, sca[j]))
                        word |= 1ULL << (j - jbase);
                }
            }
            g_mask[it] = word;
        }
    }

    // ---- epilogue: last block stages masks into SMEM, warp0 scans ----
    __threadfence();
    __syncthreads();
    if (t == 0) {
        unsigned old = atomicAdd(&g_cnt2, 1u);
        is_last = (old == PAIRB - 1u) ? 1 : 0;
    }
    __syncthreads();
    if (!is_last) return;
    __threadfence();
    __syncthreads();

    ull* smask = (ull*)dyn;
    int nwords = n * W0;
    for (int i = t; i < nwords; i += BLK) smask[i] = g_mask[i];
    __syncthreads();

    if (t < 32) {
        ull removed = 0ULL;
        int nk = 0;
        int nchunks = (n + 15) >> 4;
        for (int c = 0; c < nchunks && nk < MAXDET; c++) {
            int cb = c << 4;
            ull buf[16];
            #pragma unroll
            for (int r = 0; r < 16; r++) {
                int i = cb + r;
                buf[r] = (lane < W0 && i < n) ? smask[i * W0 + lane] : 0ULL;
            }
            int lim = min(16, n - cb);
            int widx = cb >> 6;
            ull dec = 0ULL;
            if (lane == widx) {
                ull w = removed;
                for (int r = 0; r < lim; r++) {
                    int bit = (cb + r) & 63;
                    if (!((w >> bit) & 1ULL)) {
                        dec |= 1ULL << r;
                        w |= buf[r];
                    }
                }
                removed = w;
            }
            dec = __shfl_sync(0xffffffffu, dec, widx);
            while (dec) {
                int r = __ffsll(dec) - 1;
                dec &= dec - 1;
                removed |= buf[r];
                if (lane == 0) spos[nk] = cb + r;
                nk++;
                if (nk >= MAXDET) break;
            }
        }
        __syncwarp();
        for (int k = lane; k < nk; k += 32) {
            int p = spos[k];
            g_keep[k]  = g_cidx[p];
            g_kbox[k]  = g_cbox[p];
            g_karea[k] = g_carea[p];
        }
        if (lane == 0) {
            g_nk = nk;
            g_overflow = overflow;
            g_scnt = 0;
            g_nsurv = 0;
            g_cnt2 = 0;
            g_bar = 0;
        }
    }
}

// ===========================================================================
// K3: flag (grid, 1024-thr blocks, compact survivor records) + last block:
// serial reference greedy over compact survivors + final output.
// ===========================================================================
__global__ void __launch_bounds__(BLK3)
flag_final_kernel(const float* __restrict__ cls, int A, int C,
                  float* __restrict__ out)
{
    __shared__ float4 skb[MAXDET];
    __shared__ float  ska[MAXDET];
    __shared__ ull    sb[BLK3];
    __shared__ float4 swin;
    __shared__ float  swar;
    __shared__ int    is_last;
    int t = threadIdx.x;
    int lane = t & 31;
    int wrp = t >> 5;

    // ---- flag: tail vs snapshot kept set; survivors -> compact records ----
    int nk = g_nk;
    if (nk < MAXDET) {
        for (int k = t; k < nk; k += BLK3) {
            skb[k] = g_kbox[k];
            ska[k] = g_karea[k];
        }
        __syncthreads();
        int sovf = g_overflow;
        int a = blockIdx.x * BLK3 + t;
        if (a < A) {
            float key = g_keys[a];
            if (key > PSTTHD && (sovf || !(key > CUTOFF))) {
                float4 b = g_boxes[a];
                float ar = g_areas[a];
                bool sup = false;
                for (int k = 0; k < nk; k++) {
                    if (sup_test(b.x, b.y, b.z, b.w, ar,
                                 skb[k].x, skb[k].y, skb[k].z, skb[k].w, ska[k])) {
                        sup = true;
                        break;
                    }
                }
                if (!sup) {
                    int p = atomicAdd(&g_nsurv, 1);
                    g_skey [p] = ((ull)__float_as_uint(key) << 18) |
                                 (ull)(0x3FFFFu - (unsigned)a);
                    g_sbox [p] = b;
                    g_sarea[p] = ar;
                }
            }
        }
    }

    // ---- epilogue selection ----
    __threadfence();
    __syncthreads();
    if (t == 0) {
        unsigned old = atomicAdd(&g_cnt3, 1u);
        is_last = (old == gridDim.x - 1u) ? 1 : 0;
    }
    __syncthreads();
    if (!is_last) return;
    __threadfence();

    // ---- serial reference greedy over compact survivors ----
    int nk3 = g_nk;
    int ns = g_nsurv;
    while (nk3 < MAXDET && ns > 0) {
        ull best = 0ULL;
        for (int i = t; i < ns; i += BLK3) {
            ull v = g_skey[i];
            if (v > best) best = v;
        }
        sb[t] = best;
        __syncthreads();
        for (int off = BLK3 / 2; off; off >>= 1) {
            if (t < off && sb[t + off] > sb[t]) sb[t] = sb[t + off];
            __syncthreads();
        }
        if (sb[0] == 0ULL) break;

        if (t == 0) {
            int a = (int)(0x3FFFFu - (unsigned)(sb[0] & 0x3FFFFULL));
            float4 b = g_boxes[a];
            float ar = g_areas[a];
            g_keep[nk3]  = a;
            g_kbox[nk3]  = b;
            g_karea[nk3] = ar;
            swin = b;
            swar = ar;
        }
        __syncthreads();
        float4 wb = swin;
        float war = swar;
        for (int i = t; i < ns; i += BLK3) {
            ull v = g_skey[i];
            if (v != 0ULL) {
                float4 b = g_sbox[i];
                if (sup_test(b.x, b.y, b.z, b.w, g_sarea[i],
                             wb.x, wb.y, wb.z, wb.w, war))
                    g_skey[i] = 0ULL;      // winner self-suppresses too
            }
        }
        nk3++;
        __syncthreads();
    }
    __syncthreads();

    // ---- final output: 32 warps cover 300 keeps ----
    for (int d = wrp; d < MAXDET; d += BLK3 / 32) {
        bool valid = d < nk3;
        float score = 0.f, clsid = -1.f;
        float bx0 = 0.f, bx1 = 0.f, bx2 = 0.f, bx3 = 0.f;
        if (valid) {
            int idx = g_keep[d];
            const float* row = cls + (size_t)idx * C;
            float best = -FLT_MAX;
            int bi = 0x7fffffff;
            for (int c = lane; c < C; c += 32) {
                float vv = row[c];
                if (vv > best) { best = vv; bi = c; }
            }
            #pragma unroll
            for (int off = 16; off; off >>= 1) {
                float ov = __shfl_down_sync(0xffffffffu, best, off);
                int   oi = __shfl_down_sync(0xffffffffu, bi,   off);
                if (ov > best || (ov == best && oi < bi)) { best = ov; bi = oi; }
            }
            best = __shfl_sync(0xffffffffu, best, 0);
            bi   = __shfl_sync(0xffffffffu, bi,   0);
            score = best;
            clsid = (float)bi;
            float4 b = g_kbox[d];
            bx0 = b.x; bx1 = b.y; bx2 = b.z; bx3 = b.w;
        }
        if (lane == 0) {
            out[d]                      = score;
            out[MAXDET + d]             = clsid;
            out[2 * MAXDET + 4 * d + 0] = bx0;
            out[2 * MAXDET + 4 * d + 1] = bx1;
            out[2 * MAXDET + 4 * d + 2] = bx2;
            out[2 * MAXDET + 4 * d + 3] = bx3;
            out[6 * MAXDET + d]         = valid ? 1.0f : 0.0f;
        }
    }
    __syncthreads();
    if (t == 0) g_cnt3 = 0;
}

// ---------------------------------------------------------------------------
extern "C" void kernel_launch(void* const* d_in, const int* in_sizes, int n_in,
                              void* d_out, int out_size)
{
    const float* cls = (const float*)d_in[0];
    const float* reg = (const float*)d_in[1];
    const float* anc = (const float*)d_in[2];
    const int*   ph  = (n_in > 3) ? (const int*)d_in[3] : nullptr;
    const int*   pw  = (n_in > 4) ? (const int*)d_in[4] : nullptr;

    int A = in_sizes[2] / 4;
    if (A > MAXA) A = MAXA;
    int C = in_sizes[0] / A;

    static int configured = 0;
    if (!configured) {
        cudaFuncSetAttribute(rank_pair_scan_kernel,
                             cudaFuncAttributeMaxDynamicSharedMemorySize, DSMEM);
        configured = 1;
    }

    prep_kernel<<<(A + 63) / 64, BLK>>>(cls, reg, anc, ph, pw, A, C);
    rank_pair_scan_kernel<<<PAIRB, BLK, DSMEM>>>();
    flag_final_kernel<<<(A + BLK3 - 1) / BLK3, BLK3>>>(cls, A, C, (float*)d_out);
}